// round 1
// baseline (speedup 1.0000x reference)
#include <cuda_runtime.h>
#include <cuda_bf16.h>

// ---------------------------------------------------------------------------
// weighted_loss: graph neighbor-state count -> key histogram -> weighted CE
//
// Inputs (metadata order):
//   d_in[0] : out        float32 [N,2]
//   d_in[1] : x          int32   [N]      (binary 0/1)
//   d_in[2] : y          int32   [N]      (binary 0/1)
//   d_in[3] : edge_index int32   [2,E]    (row = ei[0:E], col = ei[E:2E])
// Output: scalar float32
// ---------------------------------------------------------------------------

#define MAXN      200704            // >= N=200000, padded
#define NBITWORDS ((MAXN + 31) / 32)   // 6272 words = 25088 B bitmap
#define HSIZE     (1 << 19)         // 512K-entry histogram (2 MB, L2 resident)

__device__ unsigned int g_packed[MAXN];       // low16 = s0 (#nbrs x==1), high16 = s1
__device__ int          g_hist[HSIZE];
__device__ unsigned int g_xbits[NBITWORDS];
__device__ double       g_acc[2];             // [0] = sum(w*nll), [1] = sum(w)

// ---------------------------------------------------------------------------
__global__ void zero_kernel() {
    int i = blockIdx.x * blockDim.x + threadIdx.x;
    if (i < HSIZE) g_hist[i] = 0;
    if (i < MAXN)  g_packed[i] = 0u;
    if (i < 2)     g_acc[i] = 0.0;
}

// Build bitmap of (x > 0) via ballot: one bit per node.
__global__ void bitmap_kernel(const int* __restrict__ x, int N) {
    int i = blockIdx.x * blockDim.x + threadIdx.x;
    int v = 0;
    if (i < N) v = (x[i] > 0) ? 1 : 0;
    unsigned int bits = __ballot_sync(0xFFFFFFFFu, v);
    if ((threadIdx.x & 31) == 0) {
        int w = i >> 5;
        if (w < NBITWORDS) g_xbits[w] = bits;
    }
}

// Edge scatter: for each edge (r, c): g_packed[r] += (x[c]? 1 : 1<<16)
__global__ void __launch_bounds__(256) edge_kernel(const int* __restrict__ ei,
                                                   int N, int E) {
    __shared__ unsigned int sbits[NBITWORDS];
    int nw = (N + 31) >> 5;
    for (int w = threadIdx.x; w < nw; w += blockDim.x) sbits[w] = g_xbits[w];
    __syncthreads();

    int tid    = blockIdx.x * blockDim.x + threadIdx.x;
    int stride = gridDim.x * blockDim.x;

    if ((E & 3) == 0) {
        const int4* row4 = (const int4*)ei;
        const int4* col4 = (const int4*)(ei + E);
        int n4 = E >> 2;
        for (int i = tid; i < n4; i += stride) {
            int4 r = row4[i];
            int4 c = col4[i];
            unsigned int b, add;
            b = (sbits[((unsigned)c.x) >> 5] >> (c.x & 31)) & 1u;
            add = b ? 1u : 0x10000u;
            atomicAdd(&g_packed[r.x], add);
            b = (sbits[((unsigned)c.y) >> 5] >> (c.y & 31)) & 1u;
            add = b ? 1u : 0x10000u;
            atomicAdd(&g_packed[r.y], add);
            b = (sbits[((unsigned)c.z) >> 5] >> (c.z & 31)) & 1u;
            add = b ? 1u : 0x10000u;
            atomicAdd(&g_packed[r.z], add);
            b = (sbits[((unsigned)c.w) >> 5] >> (c.w & 31)) & 1u;
            add = b ? 1u : 0x10000u;
            atomicAdd(&g_packed[r.w], add);
        }
    } else {
        const int* rowp = ei;
        const int* colp = ei + E;
        for (int i = tid; i < E; i += stride) {
            int r = rowp[i];
            int c = colp[i];
            unsigned int b = (sbits[((unsigned)c) >> 5] >> (c & 31)) & 1u;
            atomicAdd(&g_packed[r], b ? 1u : 0x10000u);
        }
    }
}

__device__ __forceinline__ int node_key(int xv, unsigned int packed) {
    int s0 = (int)(packed & 0xFFFFu);
    int s1 = (int)(packed >> 16);
    if (s0 > 511) s0 = 511;    // degrees are ~Poisson(64); never reached
    if (s1 > 511) s1 = 511;
    return ((xv > 0) ? (1 << 18) : 0) | (s0 << 9) | s1;
}

__global__ void hist_kernel(const int* __restrict__ x, int N) {
    int i = blockIdx.x * blockDim.x + threadIdx.x;
    if (i < N) {
        int key = node_key(x[i], g_packed[i]);
        atomicAdd(&g_hist[key], 1);
    }
}

__inline__ __device__ float warp_reduce(float v) {
    #pragma unroll
    for (int o = 16; o > 0; o >>= 1) v += __shfl_down_sync(0xFFFFFFFFu, v, o);
    return v;
}

__global__ void __launch_bounds__(256) node_kernel(const float* __restrict__ out2,
                                                   const int* __restrict__ x,
                                                   const int* __restrict__ y,
                                                   int N) {
    int tid    = blockIdx.x * blockDim.x + threadIdx.x;
    int stride = gridDim.x * blockDim.x;
    float acc_wn = 0.0f, acc_w = 0.0f;
    for (int i = tid; i < N; i += stride) {
        int key = node_key(x[i], g_packed[i]);
        int cnt = g_hist[key];
        float w = rsqrtf((float)cnt);            // cnt^(-0.5)
        float o0 = out2[2 * i], o1 = out2[2 * i + 1];
        float m  = fmaxf(o0, o1);
        float lse = m + logf(expf(o0 - m) + expf(o1 - m));
        float oy  = (y[i] > 0) ? o1 : o0;
        float nll = lse - oy;
        acc_wn += nll * w;
        acc_w  += w;
    }
    // block reduce
    __shared__ float swn[8], sw[8];
    int lane = threadIdx.x & 31, wid = threadIdx.x >> 5;
    acc_wn = warp_reduce(acc_wn);
    acc_w  = warp_reduce(acc_w);
    if (lane == 0) { swn[wid] = acc_wn; sw[wid] = acc_w; }
    __syncthreads();
    if (wid == 0) {
        int nwarp = (blockDim.x + 31) >> 5;
        acc_wn = (lane < nwarp) ? swn[lane] : 0.0f;
        acc_w  = (lane < nwarp) ? sw[lane]  : 0.0f;
        acc_wn = warp_reduce(acc_wn);
        acc_w  = warp_reduce(acc_w);
        if (lane == 0) {
            atomicAdd(&g_acc[0], (double)acc_wn);
            atomicAdd(&g_acc[1], (double)acc_w);
        }
    }
}

__global__ void finalize_kernel(float* out) {
    out[0] = (float)(g_acc[0] / g_acc[1]);
}

// ---------------------------------------------------------------------------
extern "C" void kernel_launch(void* const* d_in, const int* in_sizes, int n_in,
                              void* d_out, int out_size) {
    const float* out2 = (const float*)d_in[0];
    const int*   x    = (const int*)d_in[1];
    const int*   y    = (const int*)d_in[2];
    const int*   ei   = (const int*)d_in[3];
    float* res = (float*)d_out;

    int N = in_sizes[1];
    int E = in_sizes[3] / 2;

    // 1. zero scratch (hist 512K entries dominates)
    zero_kernel<<<(HSIZE + 255) / 256, 256>>>();

    // 2. x bitmap
    bitmap_kernel<<<(N + 255) / 256, 256>>>(x, N);

    // 3. edge scatter (25KB smem/CTA -> up to 8 CTA/SM; ~1184 resident on 148 SMs)
    edge_kernel<<<1184, 256>>>(ei, N, E);

    // 4. key histogram
    hist_kernel<<<(N + 255) / 256, 256>>>(x, N);

    // 5. weighted loss reduction
    node_kernel<<<512, 256>>>(out2, x, y, N);

    // 6. scalar
    finalize_kernel<<<1, 1>>>(res);
}